// round 15
// baseline (speedup 1.0000x reference)
#include <cuda_runtime.h>
#include <cuda_fp16.h>
#include <cstdint>
#include <math.h>

// ---------------- problem constants ----------------
#define M_TOK   8192
#define IN_F    2048
#define OUT_F   2048
#define NEXP    4
#define RANK    8
#define NJ      32
#define SCALE   2.0f

// extended-K layout: [x fp16 (2048) | coef fp16 (32) | zero pad (32)]
#define KLORA0  2048
#define KEXT    2112            // 33 tiles of 64

// ---------------- device scratch (static, no allocation) ----------------
__device__ __align__(128) __half g_Aext[(size_t)M_TOK * KEXT];
__device__ __align__(128) __half g_Bext[(size_t)OUT_F * KEXT];
__device__ __align__(128) __half g_Wr[64 * IN_F];

// ---------------- helpers ----------------
__device__ __forceinline__ uint32_t smem_u32(const void* p) {
    uint32_t a;
    asm("{ .reg .u64 t; cvta.to.shared.u64 t, %1; cvt.u32.u64 %0, t; }" : "=r"(a) : "l"(p));
    return a;
}
__device__ __forceinline__ uint32_t sw128(uint32_t off) { return off ^ ((off >> 3) & 0x70); }
__device__ __forceinline__ void cp_async16(uint32_t dst, const void* src) {
    asm volatile("cp.async.cg.shared.global [%0], [%1], 16;" :: "r"(dst), "l"(src) : "memory");
}
__device__ __forceinline__ void cp_commit() {
    asm volatile("cp.async.commit_group;" ::: "memory");
}
__device__ __forceinline__ void ldsm4(uint32_t* r, uint32_t addr) {
    asm volatile("ldmatrix.sync.aligned.m8n8.x4.shared.b16 {%0,%1,%2,%3}, [%4];"
                 : "=r"(r[0]), "=r"(r[1]), "=r"(r[2]), "=r"(r[3]) : "r"(addr));
}
__device__ __forceinline__ void mma_fp16(float* c, const uint32_t* a, uint32_t b0, uint32_t b1) {
    asm volatile("mma.sync.aligned.m16n8k16.row.col.f32.f16.f16.f32 "
                 "{%0,%1,%2,%3}, {%4,%5,%6,%7}, {%8,%9}, {%0,%1,%2,%3};"
                 : "+f"(c[0]), "+f"(c[1]), "+f"(c[2]), "+f"(c[3])
                 : "r"(a[0]), "r"(a[1]), "r"(a[2]), "r"(a[3]), "r"(b0), "r"(b1));
}

// ---------------- Kernel: X -> A_ext fp16 (main columns only) ----------------
__global__ __launch_bounds__(256)
void convert_x_kernel(const float* __restrict__ X, __half* __restrict__ Aext)
{
    int i = blockIdx.x * 256 + threadIdx.x;
    const int GPR = IN_F / 4;
    int m  = i / GPR;
    int k4 = (i - m * GPR) * 4;
    float4 v = *(const float4*)(X + (size_t)m * IN_F + k4);
    __half2 h01 = __floats2half2_rn(v.x, v.y);
    __half2 h23 = __floats2half2_rn(v.z, v.w);
    size_t base = (size_t)m * KEXT + k4;
    *(__half2*)(Aext + base)     = h01;
    *(__half2*)(Aext + base + 2) = h23;
}

// ---------------- Kernel: W -> B_ext fp16, fused Bcat tail + zero-pad ----------------
__global__ __launch_bounds__(256)
void convert_w_bcat_kernel(const float* __restrict__ W, const float* __restrict__ Bm,
                           __half* __restrict__ Bext)
{
    int i = blockIdx.x * 256 + threadIdx.x;
    const int MAIN = OUT_F * (IN_F / 4);
    if (i < MAIN) {
        int n  = i >> 9;
        int k4 = (i & 511) * 4;
        float4 v = *(const float4*)(W + (size_t)n * IN_F + k4);
        __half2 h01 = __floats2half2_rn(v.x, v.y);
        __half2 h23 = __floats2half2_rn(v.z, v.w);
        size_t base = (size_t)n * KEXT + k4;
        *(__half2*)(Bext + base)     = h01;
        *(__half2*)(Bext + base + 2) = h23;
        return;
    }
    i -= MAIN;
    int n = i >> 6, j = i & 63;
    float b = 0.0f;
    if (j < NJ) {
        int e = j >> 3, r = j & 7;
        b = Bm[((size_t)e * OUT_F + n) * RANK + r];
    }
    Bext[(size_t)n * KEXT + KLORA0 + j] = __float2half_rn(b);
}

// ---------------- Kernel: pack [A(32) | Rw(4) | zeros(28)] -> Wr fp16 ----------------
__global__ __launch_bounds__(256)
void wr_pack_kernel(const float* __restrict__ A, const float* __restrict__ Rw,
                    __half* __restrict__ Wr)
{
    int i = blockIdx.x * 256 + threadIdx.x;
    int row = i >> 9;
    int k4  = (i & 511) * 4;
    float4 v = make_float4(0.f, 0.f, 0.f, 0.f);
    if (row < 32)      v = *(const float4*)(A  + (size_t)row * IN_F + k4);
    else if (row < 36) v = *(const float4*)(Rw + (size_t)(row - 32) * IN_F + k4);
    __half2 h01 = __floats2half2_rn(v.x, v.y);
    __half2 h23 = __floats2half2_rn(v.z, v.w);
    size_t base = (size_t)row * IN_F + k4;
    *(__half2*)(Wr + base)     = h01;
    *(__half2*)(Wr + base + 2) = h23;
}

// ---------------- Router: X fp32 (inline cvt) @ Wr^T -> gates -> coef tail ----------------
// Reads X directly (independent of convert_x); writes ONLY Aext cols 2048+.
#define RT_NKT (IN_F / 64)     // 32
#define RT_X0 0
#define RT_X1 8192
#define RT_W0 16384
#define RT_W1 24576

__global__ __launch_bounds__(128, 2)
void router_coef_kernel(const float* __restrict__ X,
                        const __half* __restrict__ Wr,
                        __half* __restrict__ Aext)
{
    __shared__ __align__(128) char smem[4 * 8192];
    const uint32_t s0 = smem_u32(smem);
    const int tid = threadIdx.x;
    const int w = tid >> 5, lane = tid & 31;
    const int m0 = blockIdx.x * 64;

    const int xrow = tid >> 1;
    const int xcg  = tid & 1;
    const float* xsrc = X + (size_t)(m0 + xrow) * IN_F + xcg * 32;
    uint32_t xsts[4];
#pragma unroll
    for (int i = 0; i < 4; i++)
        xsts[i] = sw128((uint32_t)(xrow * 128 + xcg * 64 + i * 16));

    const int lrow = tid >> 3, lch = tid & 7;
    uint32_t wsts[4]; const __half* wsrc[4];
#pragma unroll
    for (int r = 0; r < 4; r++) {
        int row = lrow + 16 * r;
        wsts[r] = sw128((uint32_t)(row * 128 + lch * 16));
        wsrc[r] = Wr + (size_t)row * IN_F + lch * 8;
    }

    float4 X4[8];
    auto ldg_chunk = [&](int kt) {
#pragma unroll
        for (int i = 0; i < 8; i++)
            X4[i] = *(const float4*)(xsrc + kt * 64 + i * 4);
    };
    auto cvt_store = [&](int kt) {
        const uint32_t xb = (kt & 1) ? RT_X1 : RT_X0;
#pragma unroll
        for (int j = 0; j < 4; j++) {
            __half2 h0 = __floats2half2_rn(X4[2*j].x,   X4[2*j].y);
            __half2 h1 = __floats2half2_rn(X4[2*j].z,   X4[2*j].w);
            __half2 h2 = __floats2half2_rn(X4[2*j+1].x, X4[2*j+1].y);
            __half2 h3 = __floats2half2_rn(X4[2*j+1].z, X4[2*j+1].w);
            uint32_t c[4];
            c[0] = *(uint32_t*)&h0; c[1] = *(uint32_t*)&h1;
            c[2] = *(uint32_t*)&h2; c[3] = *(uint32_t*)&h3;
            *(uint4*)(smem + xb + xsts[j]) = *(uint4*)c;
        }
    };
    auto wr_load = [&](int kt, int s) {
        const uint32_t base = s0 + (s ? RT_W1 : RT_W0);
        const int ko = kt * 64;
#pragma unroll
        for (int r = 0; r < 4; r++)
            cp_async16(base + wsts[r], wsrc[r] + ko);
        cp_commit();
    };

    float acc[8][4];
#pragma unroll
    for (int j = 0; j < 8; j++)
#pragma unroll
        for (int k = 0; k < 4; k++) acc[j][k] = 0.0f;

    ldg_chunk(0);
    cvt_store(0);
    ldg_chunk(1);
    wr_load(0, 0);
    wr_load(1, 1);

    const int arow = w * 16 + (lane & 15);
    const int brow = lane & 15;
    const int chsel = lane >> 4;

    for (int kt = 0; kt < RT_NKT; kt++) {
        if (kt < RT_NKT - 1) asm volatile("cp.async.wait_group 1;" ::: "memory");
        else                 asm volatile("cp.async.wait_group 0;" ::: "memory");
        __syncthreads();

        const uint32_t xb = s0 + ((kt & 1) ? RT_X1 : RT_X0);
        const uint32_t wb = s0 + ((kt & 1) ? RT_W1 : RT_W0);
#pragma unroll
        for (int ks = 0; ks < 4; ks++) {
            const int ch = ks * 2 + chsel;
            uint32_t a[4];
            ldsm4(a, xb + sw128(arow * 128 + ch * 16));
            uint32_t b[4][4];
#pragma unroll
            for (int q = 0; q < 4; q++)
                ldsm4(b[q], wb + sw128((q * 16 + brow) * 128 + ch * 16));
#pragma unroll
            for (int q = 0; q < 4; q++) {
                mma_fp16(acc[2*q],   a, b[q][0], b[q][2]);
                mma_fp16(acc[2*q+1], a, b[q][1], b[q][3]);
            }
        }

        if (kt + 1 < RT_NKT) cvt_store(kt + 1);
        if (kt + 2 < RT_NKT) ldg_chunk(kt + 2);

        __syncthreads();
        if (kt + 2 < RT_NKT) wr_load(kt + 2, kt & 1);
    }

    // softmax gates -> coef tail + zero pad
    const int qbase = lane & ~3;
    float La0 = __shfl_sync(0xffffffffu, acc[4][0], qbase);
    float La1 = __shfl_sync(0xffffffffu, acc[4][1], qbase);
    float Lb0 = __shfl_sync(0xffffffffu, acc[4][0], qbase | 1);
    float Lb1 = __shfl_sync(0xffffffffu, acc[4][1], qbase | 1);
    float Ma0 = __shfl_sync(0xffffffffu, acc[4][2], qbase);
    float Ma1 = __shfl_sync(0xffffffffu, acc[4][3], qbase);
    float Mb0 = __shfl_sync(0xffffffffu, acc[4][2], qbase | 1);
    float Mb1 = __shfl_sync(0xffffffffu, acc[4][3], qbase | 1);

    float g1[4], g2[4];
    {
        float mx = fmaxf(fmaxf(La0, La1), fmaxf(Lb0, Lb1));
        float e0 = __expf(La0 - mx), e1 = __expf(La1 - mx),
              e2 = __expf(Lb0 - mx), e3 = __expf(Lb1 - mx);
        float s = SCALE / (e0 + e1 + e2 + e3);
        g1[0] = e0 * s; g1[1] = e1 * s; g1[2] = e2 * s; g1[3] = e3 * s;
    }
    {
        float mx = fmaxf(fmaxf(Ma0, Ma1), fmaxf(Mb0, Mb1));
        float e0 = __expf(Ma0 - mx), e1 = __expf(Ma1 - mx),
              e2 = __expf(Mb0 - mx), e3 = __expf(Mb1 - mx);
        float s = SCALE / (e0 + e1 + e2 + e3);
        g2[0] = e0 * s; g2[1] = e1 * s; g2[2] = e2 * s; g2[3] = e3 * s;
    }

    const int t1 = m0 + w * 16 + (lane >> 2);
    const int t2 = t1 + 8;
    __half* tail1 = Aext + (size_t)t1 * KEXT + KLORA0;
    __half* tail2 = Aext + (size_t)t2 * KEXT + KLORA0;
    const int jq = (lane & 3) * 2;
#pragma unroll
    for (int nf = 0; nf < 4; nf++) {
        int j = nf * 8 + jq;
        *(__half2*)(tail1 + j) = __floats2half2_rn(acc[nf][0] * g1[nf], acc[nf][1] * g1[nf]);
        *(__half2*)(tail2 + j) = __floats2half2_rn(acc[nf][2] * g2[nf], acc[nf][3] * g2[nf]);
    }
    __half2 z; z.x = __float2half_rn(0.f); z.y = z.x;
#pragma unroll
    for (int nf = 4; nf < 8; nf++) {
        int j = nf * 8 + jq;
        *(__half2*)(tail1 + j) = z;
        *(__half2*)(tail2 + j) = z;
    }
}

// ---------------- Main GEMM: R10 config (best measured, no gate) ----------------
#define BMg 128
#define BNg 128
#define BKg 64
#define A_BYTES 16384
#define STAGE_BYTES 32768
#define GEMM_SMEM (2 * STAGE_BYTES)       // 65536
#define NKTg (KEXT / BKg)                 // 33

__global__ __launch_bounds__(256, 2)
void gemm_hmma_kernel(const __half* __restrict__ Aext,
                      const __half* __restrict__ Bext,
                      const float* __restrict__ bias,
                      float* __restrict__ out)
{
    extern __shared__ __align__(128) char smem[];
    const uint32_t s0 = smem_u32(smem);
    const int tid  = threadIdx.x;
    const int wid  = tid >> 5, lane = tid & 31;
    const int wm   = wid >> 1, wn = wid & 1;
    const int m0   = blockIdx.y * BMg, n0 = blockIdx.x * BNg;

    const int lrow = tid >> 3;
    const int lch  = tid & 7;
    uint32_t dstA[4], dstB[4];
    const __half* srcA[4]; const __half* srcB[4];
#pragma unroll
    for (int r = 0; r < 4; r++) {
        int row = lrow + 32 * r;
        dstA[r] = sw128(row * 128 + lch * 16);
        dstB[r] = A_BYTES + sw128(row * 128 + lch * 16);
        srcA[r] = Aext + (size_t)(m0 + row) * KEXT + lch * 8;
        srcB[r] = Bext + (size_t)(n0 + row) * KEXT + lch * 8;
    }

    auto load_tile = [&](int kt, int s) {
        const uint32_t base = s0 + s * STAGE_BYTES;
        const int ko = kt * BKg;
#pragma unroll
        for (int r = 0; r < 4; r++) {
            cp_async16(base + dstA[r], srcA[r] + ko);
            cp_async16(base + dstB[r], srcB[r] + ko);
        }
        cp_commit();
    };

    float acc[2][8][4];
#pragma unroll
    for (int i = 0; i < 2; i++)
#pragma unroll
        for (int j = 0; j < 8; j++)
#pragma unroll
            for (int k = 0; k < 4; k++) acc[i][j][k] = 0.0f;

    load_tile(0, 0);
    load_tile(1, 1);

    const int arow0 = wm * 32 + (lane & 15);
    const int brow  = wn * 64 + (lane & 15);
    const int chsel = lane >> 4;

    for (int kt = 0; kt < NKTg; kt++) {
        const int s = kt & 1;
        if (kt + 1 < NKTg) asm volatile("cp.async.wait_group 1;" ::: "memory");
        else               asm volatile("cp.async.wait_group 0;" ::: "memory");
        __syncthreads();

        const uint32_t base = s0 + s * STAGE_BYTES;
#pragma unroll
        for (int ks = 0; ks < 4; ks++) {
            const int ch = ks * 2 + chsel;
            uint32_t a0[4], a1[4];
            ldsm4(a0, base + sw128(arow0 * 128 + ch * 16));
            ldsm4(a1, base + sw128((arow0 + 16) * 128 + ch * 16));
            uint32_t b[4][4];
#pragma unroll
            for (int q = 0; q < 4; q++)
                ldsm4(b[q], base + A_BYTES + sw128((brow + q * 16) * 128 + ch * 16));
#pragma unroll
            for (int q = 0; q < 4; q++) {
                mma_fp16(acc[0][2*q],   a0, b[q][0], b[q][2]);
                mma_fp16(acc[0][2*q+1], a0, b[q][1], b[q][3]);
                mma_fp16(acc[1][2*q],   a1, b[q][0], b[q][2]);
                mma_fp16(acc[1][2*q+1], a1, b[q][1], b[q][3]);
            }
        }
        __syncthreads();
        if (kt + 2 < NKTg) load_tile(kt + 2, s);
    }

    // epilogue: + bias
#pragma unroll
    for (int mf = 0; mf < 2; mf++) {
        const int row = m0 + wm * 32 + mf * 16 + (lane >> 2);
#pragma unroll
        for (int nf = 0; nf < 8; nf++) {
            const int col = n0 + wn * 64 + nf * 8 + (lane & 3) * 2;
            float2 bv = *(const float2*)(bias + col);
            float2 o0, o1;
            o0.x = acc[mf][nf][0] + bv.x; o0.y = acc[mf][nf][1] + bv.y;
            o1.x = acc[mf][nf][2] + bv.x; o1.y = acc[mf][nf][3] + bv.y;
            *(float2*)(out + (size_t)row * OUT_F + col)       = o0;
            *(float2*)(out + (size_t)(row + 8) * OUT_F + col) = o1;
        }
    }
}

// ---------------- host launcher: 3-way parallel front-end, event-joined ----------------
extern "C" void kernel_launch(void* const* d_in, const int* in_sizes, int n_in,
                              void* d_out, int out_size)
{
    const float* x      = (const float*)d_in[0];
    const float* base_w = (const float*)d_in[1];
    const float* base_b = (const float*)d_in[2];
    const float* A      = (const float*)d_in[3];
    const float* Bm     = (const float*)d_in[4];
    const float* rw     = (const float*)d_in[5];
    float* out = (float*)d_out;

    __half *Aext = nullptr, *Bext = nullptr, *Wr = nullptr;
    cudaGetSymbolAddress((void**)&Aext, g_Aext);
    cudaGetSymbolAddress((void**)&Bext, g_Bext);
    cudaGetSymbolAddress((void**)&Wr,   g_Wr);

    static bool init_done = false;
    static cudaStream_t s1, s2;
    static cudaEvent_t evFork, evW, evRouter;
    if (!init_done) {
        cudaFuncSetAttribute(gemm_hmma_kernel,
                             cudaFuncAttributeMaxDynamicSharedMemorySize, GEMM_SMEM);
        cudaStreamCreateWithFlags(&s1, cudaStreamNonBlocking);
        cudaStreamCreateWithFlags(&s2, cudaStreamNonBlocking);
        cudaEventCreateWithFlags(&evFork,   cudaEventDisableTiming);
        cudaEventCreateWithFlags(&evW,      cudaEventDisableTiming);
        cudaEventCreateWithFlags(&evRouter, cudaEventDisableTiming);
        init_done = true;
    }

    // fork
    cudaEventRecord(evFork, 0);
    cudaStreamWaitEvent(s1, evFork, 0);
    cudaStreamWaitEvent(s2, evFork, 0);

    // s2: router path (reads X fp32 directly; writes ONLY Aext coef tail)
    wr_pack_kernel<<<(64 * IN_F / 4) / 256, 256, 0, s2>>>(A, rw, Wr);
    router_coef_kernel<<<M_TOK / 64, 128, 0, s2>>>(x, Wr, Aext);
    cudaEventRecord(evRouter, s2);

    // s1: B-side conversion
    {
        int total = OUT_F * (IN_F / 4) + OUT_F * 64;
        convert_w_bcat_kernel<<<(total + 255) / 256, 256, 0, s1>>>(base_w, Bm, Bext);
    }
    cudaEventRecord(evW, s1);

    // main: X conversion (Aext main cols; disjoint from router's tail writes)
    convert_x_kernel<<<(M_TOK * IN_F / 4) / 256, 256>>>(x, Aext);

    // join everything, then GEMM
    cudaStreamWaitEvent(0, evW, 0);
    cudaStreamWaitEvent(0, evRouter, 0);
    dim3 grid(OUT_F / BNg, M_TOK / BMg);   // (16, 64) = 1024 CTAs
    gemm_hmma_kernel<<<grid, 256, GEMM_SMEM>>>(Aext, Bext, base_b, out);
}

// round 16
// speedup vs baseline: 1.3418x; 1.3418x over previous
#include <cuda_runtime.h>
#include <cuda_fp16.h>
#include <cstdint>
#include <math.h>

// ---------------- problem constants ----------------
#define M_TOK   8192
#define IN_F    2048
#define OUT_F   2048
#define NEXP    4
#define RANK    8
#define NJ      32
#define SCALE   2.0f

// extended-K layout: [x fp16 (2048) | coef fp16 (32) | zero pad (32)]
#define KLORA0  2048
#define KEXT    2112            // 33 tiles of 64

// ---------------- device scratch (static, no allocation) ----------------
__device__ __align__(128) __half g_Aext[(size_t)M_TOK * KEXT];
__device__ __align__(128) __half g_Bext[(size_t)OUT_F * KEXT];
__device__ __align__(128) __half g_Wr[64 * IN_F];

// ---------------- helpers ----------------
__device__ __forceinline__ uint32_t smem_u32(const void* p) {
    uint32_t a;
    asm("{ .reg .u64 t; cvta.to.shared.u64 t, %1; cvt.u32.u64 %0, t; }" : "=r"(a) : "l"(p));
    return a;
}
__device__ __forceinline__ uint32_t sw128(uint32_t off) { return off ^ ((off >> 3) & 0x70); }
__device__ __forceinline__ void cp_async16(uint32_t dst, const void* src) {
    asm volatile("cp.async.cg.shared.global [%0], [%1], 16;" :: "r"(dst), "l"(src) : "memory");
}
__device__ __forceinline__ void cp_commit() {
    asm volatile("cp.async.commit_group;" ::: "memory");
}
__device__ __forceinline__ void ldsm4(uint32_t* r, uint32_t addr) {
    asm volatile("ldmatrix.sync.aligned.m8n8.x4.shared.b16 {%0,%1,%2,%3}, [%4];"
                 : "=r"(r[0]), "=r"(r[1]), "=r"(r[2]), "=r"(r[3]) : "r"(addr));
}
__device__ __forceinline__ void mma_fp16(float* c, const uint32_t* a, uint32_t b0, uint32_t b1) {
    asm volatile("mma.sync.aligned.m16n8k16.row.col.f32.f16.f16.f32 "
                 "{%0,%1,%2,%3}, {%4,%5,%6,%7}, {%8,%9}, {%0,%1,%2,%3};"
                 : "+f"(c[0]), "+f"(c[1]), "+f"(c[2]), "+f"(c[3])
                 : "r"(a[0]), "r"(a[1]), "r"(a[2]), "r"(a[3]), "r"(b0), "r"(b1));
}

// ---------------- Kernel: X -> A_ext fp16 (8 elems/thread, 16B stores) ----------------
__global__ __launch_bounds__(256)
void convert_x_kernel(const float* __restrict__ X, __half* __restrict__ Aext)
{
    int i = blockIdx.x * 256 + threadIdx.x;       // M_TOK*IN_F/8 = 2,097,152 -> grid 8192
    int m  = i >> 8;                              // /256 groups of 8
    int k8 = (i & 255) * 8;
    const float* src = X + (size_t)m * IN_F + k8;
    float4 v0 = *(const float4*)(src);
    float4 v1 = *(const float4*)(src + 4);
    __half2 h0 = __floats2half2_rn(v0.x, v0.y);
    __half2 h1 = __floats2half2_rn(v0.z, v0.w);
    __half2 h2 = __floats2half2_rn(v1.x, v1.y);
    __half2 h3 = __floats2half2_rn(v1.z, v1.w);
    uint4 o;
    o.x = *(uint32_t*)&h0; o.y = *(uint32_t*)&h1;
    o.z = *(uint32_t*)&h2; o.w = *(uint32_t*)&h3;
    *(uint4*)(Aext + (size_t)m * KEXT + k8) = o;
}

// ---------------- Kernel: W -> B_ext fp16, fused Bcat tail + zero-pad ----------------
__global__ __launch_bounds__(256)
void convert_w_bcat_kernel(const float* __restrict__ W, const float* __restrict__ Bm,
                           __half* __restrict__ Bext)
{
    int i = blockIdx.x * 256 + threadIdx.x;
    const int MAIN = OUT_F * (IN_F / 4);
    if (i < MAIN) {
        int n  = i >> 9;
        int k4 = (i & 511) * 4;
        float4 v = *(const float4*)(W + (size_t)n * IN_F + k4);
        __half2 h01 = __floats2half2_rn(v.x, v.y);
        __half2 h23 = __floats2half2_rn(v.z, v.w);
        size_t base = (size_t)n * KEXT + k4;
        *(__half2*)(Bext + base)     = h01;
        *(__half2*)(Bext + base + 2) = h23;
        return;
    }
    i -= MAIN;
    int n = i >> 6, j = i & 63;
    float b = 0.0f;
    if (j < NJ) {
        int e = j >> 3, r = j & 7;
        b = Bm[((size_t)e * OUT_F + n) * RANK + r];
    }
    Bext[(size_t)n * KEXT + KLORA0 + j] = __float2half_rn(b);
}

// ---------------- Kernel: pack [A(32) | Rw(4) | zeros(28)] -> Wr fp16 ----------------
__global__ __launch_bounds__(256)
void wr_pack_kernel(const float* __restrict__ A, const float* __restrict__ Rw,
                    __half* __restrict__ Wr)
{
    int i = blockIdx.x * 256 + threadIdx.x;
    int row = i >> 9;
    int k4  = (i & 511) * 4;
    float4 v = make_float4(0.f, 0.f, 0.f, 0.f);
    if (row < 32)      v = *(const float4*)(A  + (size_t)row * IN_F + k4);
    else if (row < 36) v = *(const float4*)(Rw + (size_t)(row - 32) * IN_F + k4);
    __half2 h01 = __floats2half2_rn(v.x, v.y);
    __half2 h23 = __floats2half2_rn(v.z, v.w);
    size_t base = (size_t)row * IN_F + k4;
    *(__half2*)(Wr + base)     = h01;
    *(__half2*)(Wr + base + 2) = h23;
}

// ---------------- Router GEMM, split-K: 256 threads, warps 0-3 K[0:1024], 4-7 K[1024:2048] ----------------
// Reads Aext fp16 (after convert_x). smem reduction, gates epilogue unchanged.
#define RT_ITERS 16                    // 16 iters x 64 cols per K-half
#define RT_STAGE 32768                 // per stage: X h0|X h1|W h0|W h1 = 4 x 8KB
#define RT_SMEM  (2 * RT_STAGE)        // 65536

__global__ __launch_bounds__(256)
void router_gemm_kernel(const __half* __restrict__ Aext,
                        const __half* __restrict__ Wr,
                        __half* __restrict__ AextW)
{
    extern __shared__ __align__(128) char smem[];
    const uint32_t s0 = smem_u32(smem);
    const int tid = threadIdx.x;
    const int w = tid >> 5, lane = tid & 31;
    const int grp = w & 3;            // token group (16 rows)
    const int kh  = w >> 2;           // K half
    const int m0 = blockIdx.x * 64;

    // loader: thread covers rows r1 = tid>>3 (0..31) and r1+32, lch = tid&7,
    // for X and W, both halves: 8 cp.async per iter
    const int r1  = tid >> 3;
    const int lch = tid & 7;
    const uint32_t d1 = sw128((uint32_t)(r1 * 128 + lch * 16));
    const uint32_t d2 = sw128((uint32_t)((r1 + 32) * 128 + lch * 16));
    const __half* xs1 = Aext + (size_t)(m0 + r1) * KEXT + lch * 8;
    const __half* xs2 = Aext + (size_t)(m0 + r1 + 32) * KEXT + lch * 8;
    const __half* ws1 = Wr + (size_t)r1 * IN_F + lch * 8;
    const __half* ws2 = Wr + (size_t)(r1 + 32) * IN_F + lch * 8;

    auto load_iter = [&](int it, int s) {
        const uint32_t base = s0 + s * RT_STAGE;
#pragma unroll
        for (int h = 0; h < 2; h++) {
            const int ko = h * 1024 + it * 64;
            cp_async16(base + h * 8192 + d1, xs1 + ko);
            cp_async16(base + h * 8192 + d2, xs2 + ko);
            cp_async16(base + 16384 + h * 8192 + d1, ws1 + ko);
            cp_async16(base + 16384 + h * 8192 + d2, ws2 + ko);
        }
        cp_commit();
    };

    float acc[8][4];
#pragma unroll
    for (int j = 0; j < 8; j++)
#pragma unroll
        for (int k = 0; k < 4; k++) acc[j][k] = 0.0f;

    load_iter(0, 0);
    load_iter(1, 1);

    const int arow = grp * 16 + (lane & 15);
    const int brow = lane & 15;
    const int chsel = lane >> 4;

    for (int it = 0; it < RT_ITERS; it++) {
        if (it + 1 < RT_ITERS) asm volatile("cp.async.wait_group 1;" ::: "memory");
        else                   asm volatile("cp.async.wait_group 0;" ::: "memory");
        __syncthreads();

        const uint32_t sb = s0 + (it & 1) * RT_STAGE;
        const uint32_t xb = sb + kh * 8192;
        const uint32_t wb = sb + 16384 + kh * 8192;
#pragma unroll
        for (int ks = 0; ks < 4; ks++) {
            const int ch = ks * 2 + chsel;
            uint32_t a[4];
            ldsm4(a, xb + sw128(arow * 128 + ch * 16));
            uint32_t b[4][4];
#pragma unroll
            for (int q = 0; q < 4; q++)
                ldsm4(b[q], wb + sw128((q * 16 + brow) * 128 + ch * 16));
#pragma unroll
            for (int q = 0; q < 4; q++) {
                mma_fp16(acc[2*q],   a, b[q][0], b[q][2]);
                mma_fp16(acc[2*q+1], a, b[q][1], b[q][3]);
            }
        }
        __syncthreads();
        if (it + 2 < RT_ITERS) load_iter(it + 2, it & 1);
    }

    // split-K reduction: warps 4-7 stash acc; warps 0-3 add
    __syncthreads();
    if (tid >= 128) {
        float* dst = (float*)(smem + (size_t)(tid - 128) * 128);
#pragma unroll
        for (int j = 0; j < 8; j++)
#pragma unroll
            for (int k = 0; k < 4; k++) dst[j * 4 + k] = acc[j][k];
    }
    __syncthreads();
    if (tid < 128) {
        const float* src = (const float*)(smem + (size_t)tid * 128);
#pragma unroll
        for (int j = 0; j < 8; j++)
#pragma unroll
            for (int k = 0; k < 4; k++) acc[j][k] += src[j * 4 + k];

        // softmax gates -> coef tail + zero pad (identical to validated epilogue)
        const int qbase = lane & ~3;
        float La0 = __shfl_sync(0xffffffffu, acc[4][0], qbase);
        float La1 = __shfl_sync(0xffffffffu, acc[4][1], qbase);
        float Lb0 = __shfl_sync(0xffffffffu, acc[4][0], qbase | 1);
        float Lb1 = __shfl_sync(0xffffffffu, acc[4][1], qbase | 1);
        float Ma0 = __shfl_sync(0xffffffffu, acc[4][2], qbase);
        float Ma1 = __shfl_sync(0xffffffffu, acc[4][3], qbase);
        float Mb0 = __shfl_sync(0xffffffffu, acc[4][2], qbase | 1);
        float Mb1 = __shfl_sync(0xffffffffu, acc[4][3], qbase | 1);

        float g1[4], g2[4];
        {
            float mx = fmaxf(fmaxf(La0, La1), fmaxf(Lb0, Lb1));
            float e0 = __expf(La0 - mx), e1 = __expf(La1 - mx),
                  e2 = __expf(Lb0 - mx), e3 = __expf(Lb1 - mx);
            float s = SCALE / (e0 + e1 + e2 + e3);
            g1[0] = e0 * s; g1[1] = e1 * s; g1[2] = e2 * s; g1[3] = e3 * s;
        }
        {
            float mx = fmaxf(fmaxf(Ma0, Ma1), fmaxf(Mb0, Mb1));
            float e0 = __expf(Ma0 - mx), e1 = __expf(Ma1 - mx),
                  e2 = __expf(Mb0 - mx), e3 = __expf(Mb1 - mx);
            float s = SCALE / (e0 + e1 + e2 + e3);
            g2[0] = e0 * s; g2[1] = e1 * s; g2[2] = e2 * s; g2[3] = e3 * s;
        }

        const int t1 = m0 + grp * 16 + (lane >> 2);
        const int t2 = t1 + 8;
        __half* tail1 = AextW + (size_t)t1 * KEXT + KLORA0;
        __half* tail2 = AextW + (size_t)t2 * KEXT + KLORA0;
        const int jq = (lane & 3) * 2;
#pragma unroll
        for (int nf = 0; nf < 4; nf++) {
            int j = nf * 8 + jq;
            *(__half2*)(tail1 + j) = __floats2half2_rn(acc[nf][0] * g1[nf], acc[nf][1] * g1[nf]);
            *(__half2*)(tail2 + j) = __floats2half2_rn(acc[nf][2] * g2[nf], acc[nf][3] * g2[nf]);
        }
        __half2 z; z.x = __float2half_rn(0.f); z.y = z.x;
#pragma unroll
        for (int nf = 4; nf < 8; nf++) {
            int j = nf * 8 + jq;
            *(__half2*)(tail1 + j) = z;
            *(__half2*)(tail2 + j) = z;
        }
    }
}

// ---------------- Main GEMM: R10 config (best measured, untouched) ----------------
#define BMg 128
#define BNg 128
#define BKg 64
#define A_BYTES 16384
#define STAGE_BYTES 32768
#define GEMM_SMEM (2 * STAGE_BYTES)       // 65536
#define NKTg (KEXT / BKg)                 // 33

__global__ __launch_bounds__(256, 2)
void gemm_hmma_kernel(const __half* __restrict__ Aext,
                      const __half* __restrict__ Bext,
                      const float* __restrict__ bias,
                      float* __restrict__ out)
{
    extern __shared__ __align__(128) char smem[];
    const uint32_t s0 = smem_u32(smem);
    const int tid  = threadIdx.x;
    const int wid  = tid >> 5, lane = tid & 31;
    const int wm   = wid >> 1, wn = wid & 1;
    const int m0   = blockIdx.y * BMg, n0 = blockIdx.x * BNg;

    const int lrow = tid >> 3;
    const int lch  = tid & 7;
    uint32_t dstA[4], dstB[4];
    const __half* srcA[4]; const __half* srcB[4];
#pragma unroll
    for (int r = 0; r < 4; r++) {
        int row = lrow + 32 * r;
        dstA[r] = sw128(row * 128 + lch * 16);
        dstB[r] = A_BYTES + sw128(row * 128 + lch * 16);
        srcA[r] = Aext + (size_t)(m0 + row) * KEXT + lch * 8;
        srcB[r] = Bext + (size_t)(n0 + row) * KEXT + lch * 8;
    }

    auto load_tile = [&](int kt, int s) {
        const uint32_t base = s0 + s * STAGE_BYTES;
        const int ko = kt * BKg;
#pragma unroll
        for (int r = 0; r < 4; r++) {
            cp_async16(base + dstA[r], srcA[r] + ko);
            cp_async16(base + dstB[r], srcB[r] + ko);
        }
        cp_commit();
    };

    float acc[2][8][4];
#pragma unroll
    for (int i = 0; i < 2; i++)
#pragma unroll
        for (int j = 0; j < 8; j++)
#pragma unroll
            for (int k = 0; k < 4; k++) acc[i][j][k] = 0.0f;

    load_tile(0, 0);
    load_tile(1, 1);

    const int arow0 = wm * 32 + (lane & 15);
    const int brow  = wn * 64 + (lane & 15);
    const int chsel = lane >> 4;

    for (int kt = 0; kt < NKTg; kt++) {
        const int s = kt & 1;
        if (kt + 1 < NKTg) asm volatile("cp.async.wait_group 1;" ::: "memory");
        else               asm volatile("cp.async.wait_group 0;" ::: "memory");
        __syncthreads();

        const uint32_t base = s0 + s * STAGE_BYTES;
#pragma unroll
        for (int ks = 0; ks < 4; ks++) {
            const int ch = ks * 2 + chsel;
            uint32_t a0[4], a1[4];
            ldsm4(a0, base + sw128(arow0 * 128 + ch * 16));
            ldsm4(a1, base + sw128((arow0 + 16) * 128 + ch * 16));
            uint32_t b[4][4];
#pragma unroll
            for (int q = 0; q < 4; q++)
                ldsm4(b[q], base + A_BYTES + sw128((brow + q * 16) * 128 + ch * 16));
#pragma unroll
            for (int q = 0; q < 4; q++) {
                mma_fp16(acc[0][2*q],   a0, b[q][0], b[q][2]);
                mma_fp16(acc[0][2*q+1], a0, b[q][1], b[q][3]);
                mma_fp16(acc[1][2*q],   a1, b[q][0], b[q][2]);
                mma_fp16(acc[1][2*q+1], a1, b[q][1], b[q][3]);
            }
        }
        __syncthreads();
        if (kt + 2 < NKTg) load_tile(kt + 2, s);
    }

    // epilogue: + bias
#pragma unroll
    for (int mf = 0; mf < 2; mf++) {
        const int row = m0 + wm * 32 + mf * 16 + (lane >> 2);
#pragma unroll
        for (int nf = 0; nf < 8; nf++) {
            const int col = n0 + wn * 64 + nf * 8 + (lane & 3) * 2;
            float2 bv = *(const float2*)(bias + col);
            float2 o0, o1;
            o0.x = acc[mf][nf][0] + bv.x; o0.y = acc[mf][nf][1] + bv.y;
            o1.x = acc[mf][nf][2] + bv.x; o1.y = acc[mf][nf][3] + bv.y;
            *(float2*)(out + (size_t)row * OUT_F + col)       = o0;
            *(float2*)(out + (size_t)(row + 8) * OUT_F + col) = o1;
        }
    }
}

// ---------------- host launcher (R10 structure) ----------------
extern "C" void kernel_launch(void* const* d_in, const int* in_sizes, int n_in,
                              void* d_out, int out_size)
{
    const float* x      = (const float*)d_in[0];
    const float* base_w = (const float*)d_in[1];
    const float* base_b = (const float*)d_in[2];
    const float* A      = (const float*)d_in[3];
    const float* Bm     = (const float*)d_in[4];
    const float* rw     = (const float*)d_in[5];
    float* out = (float*)d_out;

    __half *Aext = nullptr, *Bext = nullptr, *Wr = nullptr;
    cudaGetSymbolAddress((void**)&Aext, g_Aext);
    cudaGetSymbolAddress((void**)&Bext, g_Bext);
    cudaGetSymbolAddress((void**)&Wr,   g_Wr);

    static bool init_done = false;
    static cudaStream_t s1, s2;
    static cudaEvent_t evFork, evJoin1, evJoin2;
    if (!init_done) {
        cudaFuncSetAttribute(gemm_hmma_kernel,
                             cudaFuncAttributeMaxDynamicSharedMemorySize, GEMM_SMEM);
        cudaFuncSetAttribute(router_gemm_kernel,
                             cudaFuncAttributeMaxDynamicSharedMemorySize, RT_SMEM);
        cudaStreamCreateWithFlags(&s1, cudaStreamNonBlocking);
        cudaStreamCreateWithFlags(&s2, cudaStreamNonBlocking);
        cudaEventCreateWithFlags(&evFork,  cudaEventDisableTiming);
        cudaEventCreateWithFlags(&evJoin1, cudaEventDisableTiming);
        cudaEventCreateWithFlags(&evJoin2, cudaEventDisableTiming);
        init_done = true;
    }

    // fork
    cudaEventRecord(evFork, 0);
    cudaStreamWaitEvent(s1, evFork, 0);
    cudaStreamWaitEvent(s2, evFork, 0);

    // s1: B-side conversion (independent of X path)
    {
        int total = OUT_F * (IN_F / 4) + OUT_F * 64;
        convert_w_bcat_kernel<<<(total + 255) / 256, 256, 0, s1>>>(base_w, Bm, Bext);
    }
    cudaEventRecord(evJoin1, s1);

    // s2: router weight pack
    wr_pack_kernel<<<(64 * IN_F / 4) / 256, 256, 0, s2>>>(A, rw, Wr);
    cudaEventRecord(evJoin2, s2);

    // main: X conversion, then split-K router (needs Aext + Wr)
    convert_x_kernel<<<(M_TOK * IN_F / 8) / 256, 256>>>(x, Aext);
    cudaStreamWaitEvent(0, evJoin2, 0);
    router_gemm_kernel<<<M_TOK / 64, 256, RT_SMEM>>>(Aext, Wr, Aext);

    // join B-side, then fused GEMM
    cudaStreamWaitEvent(0, evJoin1, 0);
    dim3 grid(OUT_F / BNg, M_TOK / BMg);   // (16, 64) = 1024 CTAs
    gemm_hmma_kernel<<<grid, 256, GEMM_SMEM>>>(Aext, Bext, base_b, out);
}

// round 17
// speedup vs baseline: 1.4325x; 1.0676x over previous
#include <cuda_runtime.h>
#include <cuda_fp16.h>
#include <cstdint>
#include <math.h>

// ---------------- problem constants ----------------
#define M_TOK   8192
#define IN_F    2048
#define OUT_F   2048
#define NEXP    4
#define RANK    8
#define NJ      32
#define SCALE   2.0f

// extended-K layout: [x fp16 (2048) | coef fp16 (32) | zero pad (32)]
#define KLORA0  2048
#define KEXT    2112            // 33 tiles of 64

// ---------------- device scratch (static, no allocation) ----------------
__device__ __align__(128) __half g_Aext[(size_t)M_TOK * KEXT];
__device__ __align__(128) __half g_Bext[(size_t)OUT_F * KEXT];
__device__ __align__(128) __half g_Wr[64 * IN_F];

// ---------------- helpers ----------------
__device__ __forceinline__ uint32_t smem_u32(const void* p) {
    uint32_t a;
    asm("{ .reg .u64 t; cvta.to.shared.u64 t, %1; cvt.u32.u64 %0, t; }" : "=r"(a) : "l"(p));
    return a;
}
__device__ __forceinline__ uint32_t sw128(uint32_t off) { return off ^ ((off >> 3) & 0x70); }
__device__ __forceinline__ void cp_async16(uint32_t dst, const void* src) {
    asm volatile("cp.async.cg.shared.global [%0], [%1], 16;" :: "r"(dst), "l"(src) : "memory");
}
__device__ __forceinline__ void cp_commit() {
    asm volatile("cp.async.commit_group;" ::: "memory");
}
__device__ __forceinline__ void ldsm4(uint32_t* r, uint32_t addr) {
    asm volatile("ldmatrix.sync.aligned.m8n8.x4.shared.b16 {%0,%1,%2,%3}, [%4];"
                 : "=r"(r[0]), "=r"(r[1]), "=r"(r[2]), "=r"(r[3]) : "r"(addr));
}
__device__ __forceinline__ void mma_fp16(float* c, const uint32_t* a, uint32_t b0, uint32_t b1) {
    asm volatile("mma.sync.aligned.m16n8k16.row.col.f32.f16.f16.f32 "
                 "{%0,%1,%2,%3}, {%4,%5,%6,%7}, {%8,%9}, {%0,%1,%2,%3};"
                 : "+f"(c[0]), "+f"(c[1]), "+f"(c[2]), "+f"(c[3])
                 : "r"(a[0]), "r"(a[1]), "r"(a[2]), "r"(a[3]), "r"(b0), "r"(b1));
}

// ---------------- Kernel: X -> A_ext fp16 (8 elems/thread, 16B stores) ----------------
__global__ __launch_bounds__(256)
void convert_x_kernel(const float* __restrict__ X, __half* __restrict__ Aext)
{
    int i = blockIdx.x * 256 + threadIdx.x;
    int m  = i >> 8;
    int k8 = (i & 255) * 8;
    const float* src = X + (size_t)m * IN_F + k8;
    float4 v0 = *(const float4*)(src);
    float4 v1 = *(const float4*)(src + 4);
    __half2 h0 = __floats2half2_rn(v0.x, v0.y);
    __half2 h1 = __floats2half2_rn(v0.z, v0.w);
    __half2 h2 = __floats2half2_rn(v1.x, v1.y);
    __half2 h3 = __floats2half2_rn(v1.z, v1.w);
    uint4 o;
    o.x = *(uint32_t*)&h0; o.y = *(uint32_t*)&h1;
    o.z = *(uint32_t*)&h2; o.w = *(uint32_t*)&h3;
    *(uint4*)(Aext + (size_t)m * KEXT + k8) = o;
}

// ---------------- Kernel: W -> B_ext fp16, fused Bcat tail + zero-pad ----------------
__global__ __launch_bounds__(256)
void convert_w_bcat_kernel(const float* __restrict__ W, const float* __restrict__ Bm,
                           __half* __restrict__ Bext)
{
    int i = blockIdx.x * 256 + threadIdx.x;
    const int MAIN = OUT_F * (IN_F / 4);
    if (i < MAIN) {
        int n  = i >> 9;
        int k4 = (i & 511) * 4;
        float4 v = *(const float4*)(W + (size_t)n * IN_F + k4);
        __half2 h01 = __floats2half2_rn(v.x, v.y);
        __half2 h23 = __floats2half2_rn(v.z, v.w);
        size_t base = (size_t)n * KEXT + k4;
        *(__half2*)(Bext + base)     = h01;
        *(__half2*)(Bext + base + 2) = h23;
        return;
    }
    i -= MAIN;
    int n = i >> 6, j = i & 63;
    float b = 0.0f;
    if (j < NJ) {
        int e = j >> 3, r = j & 7;
        b = Bm[((size_t)e * OUT_F + n) * RANK + r];
    }
    Bext[(size_t)n * KEXT + KLORA0 + j] = __float2half_rn(b);
}

// ---------------- Kernel: pack [A(32) | Rw(4) | zeros(28)] -> Wr fp16 ----------------
__global__ __launch_bounds__(256)
void wr_pack_kernel(const float* __restrict__ A, const float* __restrict__ Rw,
                    __half* __restrict__ Wr)
{
    int i = blockIdx.x * 256 + threadIdx.x;
    int row = i >> 9;
    int k4  = (i & 511) * 4;
    float4 v = make_float4(0.f, 0.f, 0.f, 0.f);
    if (row < 32)      v = *(const float4*)(A  + (size_t)row * IN_F + k4);
    else if (row < 36) v = *(const float4*)(Rw + (size_t)(row - 32) * IN_F + k4);
    __half2 h01 = __floats2half2_rn(v.x, v.y);
    __half2 h23 = __floats2half2_rn(v.z, v.w);
    size_t base = (size_t)row * IN_F + k4;
    *(__half2*)(Wr + base)     = h01;
    *(__half2*)(Wr + base + 2) = h23;
}

// ---------------- Router GEMM, 4-way split-K: grid 256, 32 tokens/CTA ----------------
// 8 warps: grp = w&1 (token group of 16), kh = w>>1 (K quarter of 512).
// smem stage: X 4x4KB | W 4x8KB = 48KB, 2 stages = 96KB. 8 iters of 64 cols/quarter.
#define RT_ITERS 8
#define RT_X_BYTES 16384
#define RT_STAGE 49152
#define RT_SMEM (2 * RT_STAGE)          // 98304

__global__ __launch_bounds__(256)
void router_gemm_kernel(const __half* __restrict__ Aext,
                        const __half* __restrict__ Wr,
                        __half* __restrict__ AextW)
{
    extern __shared__ __align__(128) char smem[];
    const uint32_t s0 = smem_u32(smem);
    const int tid = threadIdx.x;
    const int w = tid >> 5, lane = tid & 31;
    const int grp = w & 1;            // token group (16 rows)
    const int kh  = w >> 1;           // K quarter (512 cols)
    const int m0 = blockIdx.x * 32;

    // loaders: X one chunk/quarter (32 rows), W two chunks/quarter (64 rows)
    const int xr  = tid >> 3;         // 0..31
    const int lch = tid & 7;
    const uint32_t xd  = sw128((uint32_t)(xr * 128 + lch * 16));
    const uint32_t wd2 = sw128((uint32_t)((xr + 32) * 128 + lch * 16));
    const __half* xsrc = Aext + (size_t)(m0 + xr) * KEXT + lch * 8;
    const __half* ws1  = Wr + (size_t)xr * IN_F + lch * 8;
    const __half* ws2  = Wr + (size_t)(xr + 32) * IN_F + lch * 8;

    auto load_iter = [&](int it, int s) {
        const uint32_t base = s0 + s * RT_STAGE;
#pragma unroll
        for (int q = 0; q < 4; q++) {
            const int ko = q * 512 + it * 64;
            cp_async16(base + q * 4096 + xd, xsrc + ko);
            cp_async16(base + RT_X_BYTES + q * 8192 + xd,  ws1 + ko);
            cp_async16(base + RT_X_BYTES + q * 8192 + wd2, ws2 + ko);
        }
        cp_commit();
    };

    float acc[8][4];
#pragma unroll
    for (int j = 0; j < 8; j++)
#pragma unroll
        for (int k = 0; k < 4; k++) acc[j][k] = 0.0f;

    load_iter(0, 0);
    load_iter(1, 1);

    const int arow = grp * 16 + (lane & 15);
    const int brow = lane & 15;
    const int chsel = lane >> 4;

    for (int it = 0; it < RT_ITERS; it++) {
        if (it + 1 < RT_ITERS) asm volatile("cp.async.wait_group 1;" ::: "memory");
        else                   asm volatile("cp.async.wait_group 0;" ::: "memory");
        __syncthreads();

        const uint32_t sb = s0 + (it & 1) * RT_STAGE;
        const uint32_t xb = sb + kh * 4096;
        const uint32_t wb = sb + RT_X_BYTES + kh * 8192;
#pragma unroll
        for (int ks = 0; ks < 4; ks++) {
            const int ch = ks * 2 + chsel;
            uint32_t a[4];
            ldsm4(a, xb + sw128(arow * 128 + ch * 16));
            uint32_t b[4][4];
#pragma unroll
            for (int q = 0; q < 4; q++)
                ldsm4(b[q], wb + sw128((q * 16 + brow) * 128 + ch * 16));
#pragma unroll
            for (int q = 0; q < 4; q++) {
                mma_fp16(acc[2*q],   a, b[q][0], b[q][2]);
                mma_fp16(acc[2*q+1], a, b[q][1], b[q][3]);
            }
        }
        __syncthreads();
        if (it + 2 < RT_ITERS) load_iter(it + 2, it & 1);
    }

    // split-K reduction: warps 2-7 stash (conflict-free transposed layout); warps 0-1 add
    __syncthreads();
    if (w >= 2) {
        float* dst = (float*)(smem + (size_t)(w - 2) * 4096);
#pragma unroll
        for (int j = 0; j < 8; j++)
#pragma unroll
            for (int k = 0; k < 4; k++) dst[(j * 4 + k) * 32 + lane] = acc[j][k];
    }
    __syncthreads();
    if (w < 2) {
#pragma unroll
        for (int q = 1; q < 4; q++) {
            const float* src = (const float*)(smem + (size_t)(q * 2 + w - 2) * 4096);
#pragma unroll
            for (int j = 0; j < 8; j++)
#pragma unroll
                for (int k = 0; k < 4; k++) acc[j][k] += src[(j * 4 + k) * 32 + lane];
        }

        // softmax gates -> coef tail + zero pad (validated epilogue)
        const int qbase = lane & ~3;
        float La0 = __shfl_sync(0xffffffffu, acc[4][0], qbase);
        float La1 = __shfl_sync(0xffffffffu, acc[4][1], qbase);
        float Lb0 = __shfl_sync(0xffffffffu, acc[4][0], qbase | 1);
        float Lb1 = __shfl_sync(0xffffffffu, acc[4][1], qbase | 1);
        float Ma0 = __shfl_sync(0xffffffffu, acc[4][2], qbase);
        float Ma1 = __shfl_sync(0xffffffffu, acc[4][3], qbase);
        float Mb0 = __shfl_sync(0xffffffffu, acc[4][2], qbase | 1);
        float Mb1 = __shfl_sync(0xffffffffu, acc[4][3], qbase | 1);

        float g1[4], g2[4];
        {
            float mx = fmaxf(fmaxf(La0, La1), fmaxf(Lb0, Lb1));
            float e0 = __expf(La0 - mx), e1 = __expf(La1 - mx),
                  e2 = __expf(Lb0 - mx), e3 = __expf(Lb1 - mx);
            float s = SCALE / (e0 + e1 + e2 + e3);
            g1[0] = e0 * s; g1[1] = e1 * s; g1[2] = e2 * s; g1[3] = e3 * s;
        }
        {
            float mx = fmaxf(fmaxf(Ma0, Ma1), fmaxf(Mb0, Mb1));
            float e0 = __expf(Ma0 - mx), e1 = __expf(Ma1 - mx),
                  e2 = __expf(Mb0 - mx), e3 = __expf(Mb1 - mx);
            float s = SCALE / (e0 + e1 + e2 + e3);
            g2[0] = e0 * s; g2[1] = e1 * s; g2[2] = e2 * s; g2[3] = e3 * s;
        }

        const int t1 = m0 + grp * 16 + (lane >> 2);
        const int t2 = t1 + 8;
        __half* tail1 = AextW + (size_t)t1 * KEXT + KLORA0;
        __half* tail2 = AextW + (size_t)t2 * KEXT + KLORA0;
        const int jq = (lane & 3) * 2;
#pragma unroll
        for (int nf = 0; nf < 4; nf++) {
            int j = nf * 8 + jq;
            *(__half2*)(tail1 + j) = __floats2half2_rn(acc[nf][0] * g1[nf], acc[nf][1] * g1[nf]);
            *(__half2*)(tail2 + j) = __floats2half2_rn(acc[nf][2] * g2[nf], acc[nf][3] * g2[nf]);
        }
        __half2 z; z.x = __float2half_rn(0.f); z.y = z.x;
#pragma unroll
        for (int nf = 4; nf < 8; nf++) {
            int j = nf * 8 + jq;
            *(__half2*)(tail1 + j) = z;
            *(__half2*)(tail2 + j) = z;
        }
    }
}

// ---------------- Main GEMM: R10 config + exact last-tile peel ----------------
#define BMg 128
#define BNg 128
#define BKg 64
#define A_BYTES 16384
#define STAGE_BYTES 32768
#define GEMM_SMEM (2 * STAGE_BYTES)       // 65536
#define NKTg (KEXT / BKg)                 // 33

__global__ __launch_bounds__(256, 2)
void gemm_hmma_kernel(const __half* __restrict__ Aext,
                      const __half* __restrict__ Bext,
                      const float* __restrict__ bias,
                      float* __restrict__ out)
{
    extern __shared__ __align__(128) char smem[];
    const uint32_t s0 = smem_u32(smem);
    const int tid  = threadIdx.x;
    const int wid  = tid >> 5, lane = tid & 31;
    const int wm   = wid >> 1, wn = wid & 1;
    const int m0   = blockIdx.y * BMg, n0 = blockIdx.x * BNg;

    const int lrow = tid >> 3;
    const int lch  = tid & 7;
    uint32_t dstA[4], dstB[4];
    const __half* srcA[4]; const __half* srcB[4];
#pragma unroll
    for (int r = 0; r < 4; r++) {
        int row = lrow + 32 * r;
        dstA[r] = sw128(row * 128 + lch * 16);
        dstB[r] = A_BYTES + sw128(row * 128 + lch * 16);
        srcA[r] = Aext + (size_t)(m0 + row) * KEXT + lch * 8;
        srcB[r] = Bext + (size_t)(n0 + row) * KEXT + lch * 8;
    }

    auto load_tile = [&](int kt, int s) {
        const uint32_t base = s0 + s * STAGE_BYTES;
        const int ko = kt * BKg;
#pragma unroll
        for (int r = 0; r < 4; r++) {
            cp_async16(base + dstA[r], srcA[r] + ko);
            cp_async16(base + dstB[r], srcB[r] + ko);
        }
        cp_commit();
    };

    float acc[2][8][4];
#pragma unroll
    for (int i = 0; i < 2; i++)
#pragma unroll
        for (int j = 0; j < 8; j++)
#pragma unroll
            for (int k = 0; k < 4; k++) acc[i][j][k] = 0.0f;

    load_tile(0, 0);
    load_tile(1, 1);

    const int arow0 = wm * 32 + (lane & 15);
    const int brow  = wn * 64 + (lane & 15);
    const int chsel = lane >> 4;

    auto do_ks = [&](uint32_t base, int ks) {
        const int ch = ks * 2 + chsel;
        uint32_t a0[4], a1[4];
        ldsm4(a0, base + sw128(arow0 * 128 + ch * 16));
        ldsm4(a1, base + sw128((arow0 + 16) * 128 + ch * 16));
        uint32_t b[4][4];
#pragma unroll
        for (int q = 0; q < 4; q++)
            ldsm4(b[q], base + A_BYTES + sw128((brow + q * 16) * 128 + ch * 16));
#pragma unroll
        for (int q = 0; q < 4; q++) {
            mma_fp16(acc[0][2*q],   a0, b[q][0], b[q][2]);
            mma_fp16(acc[0][2*q+1], a0, b[q][1], b[q][3]);
            mma_fp16(acc[1][2*q],   a1, b[q][0], b[q][2]);
            mma_fp16(acc[1][2*q+1], a1, b[q][1], b[q][3]);
        }
    };

    for (int kt = 0; kt < NKTg - 1; kt++) {
        asm volatile("cp.async.wait_group 1;" ::: "memory");
        __syncthreads();
        const uint32_t base = s0 + (kt & 1) * STAGE_BYTES;
#pragma unroll
        for (int ks = 0; ks < 4; ks++) do_ks(base, ks);
        __syncthreads();
        if (kt + 2 < NKTg) load_tile(kt + 2, kt & 1);
    }
    // last tile (kt=32): K cols 2080-2111 are exact zeros -> only ks 0,1 needed
    {
        asm volatile("cp.async.wait_group 0;" ::: "memory");
        __syncthreads();
        const uint32_t base = s0 + ((NKTg - 1) & 1) * STAGE_BYTES;
        do_ks(base, 0);
        do_ks(base, 1);
    }

    // epilogue: + bias
#pragma unroll
    for (int mf = 0; mf < 2; mf++) {
        const int row = m0 + wm * 32 + mf * 16 + (lane >> 2);
#pragma unroll
        for (int nf = 0; nf < 8; nf++) {
            const int col = n0 + wn * 64 + nf * 8 + (lane & 3) * 2;
            float2 bv = *(const float2*)(bias + col);
            float2 o0, o1;
            o0.x = acc[mf][nf][0] + bv.x; o0.y = acc[mf][nf][1] + bv.y;
            o1.x = acc[mf][nf][2] + bv.x; o1.y = acc[mf][nf][3] + bv.y;
            *(float2*)(out + (size_t)row * OUT_F + col)       = o0;
            *(float2*)(out + (size_t)(row + 8) * OUT_F + col) = o1;
        }
    }
}

// ---------------- host launcher (R10/R16 structure) ----------------
extern "C" void kernel_launch(void* const* d_in, const int* in_sizes, int n_in,
                              void* d_out, int out_size)
{
    const float* x      = (const float*)d_in[0];
    const float* base_w = (const float*)d_in[1];
    const float* base_b = (const float*)d_in[2];
    const float* A      = (const float*)d_in[3];
    const float* Bm     = (const float*)d_in[4];
    const float* rw     = (const float*)d_in[5];
    float* out = (float*)d_out;

    __half *Aext = nullptr, *Bext = nullptr, *Wr = nullptr;
    cudaGetSymbolAddress((void**)&Aext, g_Aext);
    cudaGetSymbolAddress((void**)&Bext, g_Bext);
    cudaGetSymbolAddress((void**)&Wr,   g_Wr);

    static bool init_done = false;
    static cudaStream_t s1, s2;
    static cudaEvent_t evFork, evJoin1, evJoin2;
    if (!init_done) {
        cudaFuncSetAttribute(gemm_hmma_kernel,
                             cudaFuncAttributeMaxDynamicSharedMemorySize, GEMM_SMEM);
        cudaFuncSetAttribute(router_gemm_kernel,
                             cudaFuncAttributeMaxDynamicSharedMemorySize, RT_SMEM);
        cudaStreamCreateWithFlags(&s1, cudaStreamNonBlocking);
        cudaStreamCreateWithFlags(&s2, cudaStreamNonBlocking);
        cudaEventCreateWithFlags(&evFork,  cudaEventDisableTiming);
        cudaEventCreateWithFlags(&evJoin1, cudaEventDisableTiming);
        cudaEventCreateWithFlags(&evJoin2, cudaEventDisableTiming);
        init_done = true;
    }

    // fork
    cudaEventRecord(evFork, 0);
    cudaStreamWaitEvent(s1, evFork, 0);
    cudaStreamWaitEvent(s2, evFork, 0);

    // s1: B-side conversion (independent of X path)
    {
        int total = OUT_F * (IN_F / 4) + OUT_F * 64;
        convert_w_bcat_kernel<<<(total + 255) / 256, 256, 0, s1>>>(base_w, Bm, Bext);
    }
    cudaEventRecord(evJoin1, s1);

    // s2: router weight pack
    wr_pack_kernel<<<(64 * IN_F / 4) / 256, 256, 0, s2>>>(A, rw, Wr);
    cudaEventRecord(evJoin2, s2);

    // main: X conversion, then 4-way split-K router (needs Aext + Wr)
    convert_x_kernel<<<(M_TOK * IN_F / 8) / 256, 256>>>(x, Aext);
    cudaStreamWaitEvent(0, evJoin2, 0);
    router_gemm_kernel<<<M_TOK / 32, 256, RT_SMEM>>>(Aext, Wr, Aext);

    // join B-side, then fused GEMM
    cudaStreamWaitEvent(0, evJoin1, 0);
    dim3 grid(OUT_F / BNg, M_TOK / BMg);   // (16, 64) = 1024 CTAs
    gemm_hmma_kernel<<<grid, 256, GEMM_SMEM>>>(Aext, Bext, base_b, out);
}